// round 1
// baseline (speedup 1.0000x reference)
#include <cuda_runtime.h>
#include <cuda_bf16.h>
#include <cstdint>

// Problem constants
#define B_  2
#define S_  2048
#define D_  1024
#define H_  16
#define HD_ 64
#define TOK (B_*S_)   // 4096 tokens

// Scratch (allocation-free: __device__ globals)
__device__ float g_qp[B_*H_*S_*HD_];   // [B,H,S,HD]
__device__ float g_kp[B_*H_*S_*HD_];
__device__ float g_vp[B_*H_*S_*HD_];
__device__ float g_ctx[TOK*D_];        // [B,S,D] merged heads

// ---------------------------------------------------------------------------
// tf32 helpers
// ---------------------------------------------------------------------------
__device__ __forceinline__ float tf32r(float x){
    unsigned u; asm("cvt.rna.tf32.f32 %0, %1;" : "=r"(u) : "f"(x));
    return __uint_as_float(u);
}

__device__ __forceinline__ void mma8(float c[4], const float a[4], const float b[2]){
    asm volatile(
        "mma.sync.aligned.m16n8k8.row.col.f32.tf32.tf32.f32 "
        "{%0,%1,%2,%3},{%4,%5,%6,%7},{%8,%9},{%0,%1,%2,%3};\n"
        : "+f"(c[0]), "+f"(c[1]), "+f"(c[2]), "+f"(c[3])
        : "r"(__float_as_uint(a[0])), "r"(__float_as_uint(a[1])),
          "r"(__float_as_uint(a[2])), "r"(__float_as_uint(a[3])),
          "r"(__float_as_uint(b[0])), "r"(__float_as_uint(b[1])));
}

// ---------------------------------------------------------------------------
// GEMM core: C[M,N] = X[M,K] @ W[N,K]^T + bias, M=4096, N=K=1024.
// 128x128 block tile, BK=16, 256 threads (8 warps, warp tile 64x32).
// Split-tf32 (3 mma) for ~fp32 accuracy.
// SPLIT=true writes to head-split layout [B,H,S,HD]; false writes [M,N].
// ---------------------------------------------------------------------------
template<bool SPLIT>
__device__ __forceinline__ void gemm_core(const float* __restrict__ X,
                                          const float* __restrict__ W,
                                          const float* __restrict__ bias,
                                          float* __restrict__ C)
{
    __shared__ float Ah[128][20];
    __shared__ float Al[128][20];
    __shared__ float Wh[128][20];
    __shared__ float Wl[128][20];

    const int tid  = threadIdx.x;
    const int lane = tid & 31;
    const int wrp  = tid >> 5;
    const int wm   = wrp & 1;        // 0..1  (M dir, 64 each)
    const int wn   = wrp >> 1;       // 0..3  (N dir, 32 each)
    const int m0   = blockIdx.y * 128;
    const int n0   = blockIdx.x * 128;

    float acc[4][4][4] = {};

    for (int k0 = 0; k0 < D_; k0 += 16){
        __syncthreads();
        #pragma unroll
        for (int p = 0; p < 2; p++){
            int flat = tid + p*256;             // 0..511 float4 slots
            int r  = flat >> 2;
            int cg = (flat & 3) << 2;
            float4 xa = *reinterpret_cast<const float4*>(X + (size_t)(m0+r)*D_ + k0 + cg);
            float4 wa = *reinterpret_cast<const float4*>(W + (size_t)(n0+r)*D_ + k0 + cg);
            float h;
            h = tf32r(xa.x); Ah[r][cg+0]=h; Al[r][cg+0]=tf32r(xa.x-h);
            h = tf32r(xa.y); Ah[r][cg+1]=h; Al[r][cg+1]=tf32r(xa.y-h);
            h = tf32r(xa.z); Ah[r][cg+2]=h; Al[r][cg+2]=tf32r(xa.z-h);
            h = tf32r(xa.w); Ah[r][cg+3]=h; Al[r][cg+3]=tf32r(xa.w-h);
            h = tf32r(wa.x); Wh[r][cg+0]=h; Wl[r][cg+0]=tf32r(wa.x-h);
            h = tf32r(wa.y); Wh[r][cg+1]=h; Wl[r][cg+1]=tf32r(wa.y-h);
            h = tf32r(wa.z); Wh[r][cg+2]=h; Wl[r][cg+2]=tf32r(wa.z-h);
            h = tf32r(wa.w); Wh[r][cg+3]=h; Wl[r][cg+3]=tf32r(wa.w-h);
        }
        __syncthreads();

        #pragma unroll
        for (int kk = 0; kk < 2; kk++){
            const int kb = kk*8 + (lane & 3);
            float ah[4][4], al[4][4], bh[4][2], bl[4][2];
            #pragma unroll
            for (int mi = 0; mi < 4; mi++){
                int r = wm*64 + mi*16 + (lane >> 2);
                ah[mi][0]=Ah[r][kb];   ah[mi][1]=Ah[r+8][kb];
                ah[mi][2]=Ah[r][kb+4]; ah[mi][3]=Ah[r+8][kb+4];
                al[mi][0]=Al[r][kb];   al[mi][1]=Al[r+8][kb];
                al[mi][2]=Al[r][kb+4]; al[mi][3]=Al[r+8][kb+4];
            }
            #pragma unroll
            for (int ni = 0; ni < 4; ni++){
                int r = wn*32 + ni*8 + (lane >> 2);
                bh[ni][0]=Wh[r][kb]; bh[ni][1]=Wh[r][kb+4];
                bl[ni][0]=Wl[r][kb]; bl[ni][1]=Wl[r][kb+4];
            }
            #pragma unroll
            for (int mi = 0; mi < 4; mi++)
                #pragma unroll
                for (int ni = 0; ni < 4; ni++){
                    mma8(acc[mi][ni], ah[mi], bh[ni]);
                    mma8(acc[mi][ni], ah[mi], bl[ni]);
                    mma8(acc[mi][ni], al[mi], bh[ni]);
                }
        }
    }

    // epilogue
    #pragma unroll
    for (int mi = 0; mi < 4; mi++){
        #pragma unroll
        for (int ni = 0; ni < 4; ni++){
            int mrow = m0 + wm*64 + mi*16 + (lane >> 2);
            int ncol = n0 + wn*32 + ni*8 + (lane & 3)*2;
            #pragma unroll
            for (int e = 0; e < 4; e++){
                int row = mrow + ((e >= 2) ? 8 : 0);
                int col = ncol + (e & 1);
                float v = acc[mi][ni][e] + bias[col];
                if (SPLIT){
                    int b  = row >> 11;         // /S_
                    int s  = row & (S_-1);
                    int hh = col >> 6;          // /HD_
                    int hd = col & (HD_-1);
                    C[(((size_t)(b*H_+hh))*S_ + s)*HD_ + hd] = v;
                } else {
                    C[(size_t)row*D_ + col] = v;
                }
            }
        }
    }
}

__global__ __launch_bounds__(256) void proj_kernel(
    const float* __restrict__ xq, const float* __restrict__ xk, const float* __restrict__ xv,
    const float* __restrict__ wq, const float* __restrict__ wk, const float* __restrict__ wv,
    const float* __restrict__ bq, const float* __restrict__ bk, const float* __restrict__ bv)
{
    int z = blockIdx.z;
    const float* X    = (z==0) ? xq : (z==1) ? xk : xv;
    const float* W    = (z==0) ? wq : (z==1) ? wk : wv;
    const float* bias = (z==0) ? bq : (z==1) ? bk : bv;
    float*       C    = (z==0) ? g_qp : (z==1) ? g_kp : g_vp;
    gemm_core<true>(X, W, bias, C);
}

__global__ __launch_bounds__(256) void outproj_kernel(
    const float* __restrict__ wo, const float* __restrict__ bo, float* __restrict__ out)
{
    gemm_core<false>(g_ctx, wo, bo, out);
}

// ---------------------------------------------------------------------------
// Flash attention, causal. One CTA = 64 q rows x one (b,h). 4 warps x 16 rows.
// tf32 single-pass QK^T and PV, fp32 online softmax. Causal tile skip (kt<=qt).
// ---------------------------------------------------------------------------
#define KS_STRIDE 68
#define VS_STRIDE 72
#define PS_STRIDE 68
#define ATTN_SMEM ((64*KS_STRIDE + 64*VS_STRIDE + 64*PS_STRIDE)*4)

__global__ __launch_bounds__(128) void attn_kernel()
{
    extern __shared__ float sm[];
    float* Ks = sm;
    float* Vs = sm + 64*KS_STRIDE;
    float* Ps = Vs + 64*VS_STRIDE;

    const int tid  = threadIdx.x;
    const int lane = tid & 31;
    const int wrp  = tid >> 5;
    const int qt   = blockIdx.x;
    const int bh   = blockIdx.y;

    const float* Qg = g_qp + (size_t)bh * S_ * HD_;
    const float* Kg = g_kp + (size_t)bh * S_ * HD_;
    const float* Vg = g_vp + (size_t)bh * S_ * HD_;

    const int qr = qt*64 + wrp*16 + (lane >> 2);   // global q row (pair base)
    const int pr = wrp*16 + (lane >> 2);           // local row within CTA

    // Q fragments resident in registers for the whole kernel (scale 1/8 folded in)
    float qa[8][4];
    #pragma unroll
    for (int kf = 0; kf < 8; kf++){
        int cc = kf*8 + (lane & 3);
        qa[kf][0] = tf32r(0.125f * Qg[(size_t)qr    *HD_ + cc    ]);
        qa[kf][1] = tf32r(0.125f * Qg[(size_t)(qr+8)*HD_ + cc    ]);
        qa[kf][2] = tf32r(0.125f * Qg[(size_t)qr    *HD_ + cc + 4]);
        qa[kf][3] = tf32r(0.125f * Qg[(size_t)(qr+8)*HD_ + cc + 4]);
    }

    float o[8][4] = {};
    float mr0 = -1e30f, mr1 = -1e30f, l0 = 0.f, l1 = 0.f;

    for (int kt = 0; kt <= qt; kt++){
        __syncthreads();
        #pragma unroll
        for (int p = 0; p < 8; p++){
            int flat = tid + p*128;                // 0..1023 float4 slots
            int r  = flat >> 4;
            int cg = (flat & 15) << 2;
            float4 k4 = *reinterpret_cast<const float4*>(Kg + (size_t)(kt*64+r)*HD_ + cg);
            float4 v4 = *reinterpret_cast<const float4*>(Vg + (size_t)(kt*64+r)*HD_ + cg);
            Ks[r*KS_STRIDE+cg+0]=tf32r(k4.x); Ks[r*KS_STRIDE+cg+1]=tf32r(k4.y);
            Ks[r*KS_STRIDE+cg+2]=tf32r(k4.z); Ks[r*KS_STRIDE+cg+3]=tf32r(k4.w);
            Vs[r*VS_STRIDE+cg+0]=tf32r(v4.x); Vs[r*VS_STRIDE+cg+1]=tf32r(v4.y);
            Vs[r*VS_STRIDE+cg+2]=tf32r(v4.z); Vs[r*VS_STRIDE+cg+3]=tf32r(v4.w);
        }
        __syncthreads();

        // scores: S = Q @ K^T  (64x64, K-dim = HD = 64)
        float sc[8][4] = {};
        #pragma unroll
        for (int kf = 0; kf < 8; kf++){
            #pragma unroll
            for (int jn = 0; jn < 8; jn++){
                float b[2];
                int krow = jn*8 + (lane >> 2);
                int kc   = kf*8 + (lane & 3);
                b[0] = Ks[krow*KS_STRIDE + kc];
                b[1] = Ks[krow*KS_STRIDE + kc + 4];
                mma8(sc[jn], qa[kf], b);
            }
        }

        // causal mask on diagonal tile only
        if (kt == qt){
            #pragma unroll
            for (int jn = 0; jn < 8; jn++){
                int cb = kt*64 + jn*8 + (lane & 3)*2;
                if (cb   > qr  ) sc[jn][0] = -1e30f;
                if (cb+1 > qr  ) sc[jn][1] = -1e30f;
                if (cb   > qr+8) sc[jn][2] = -1e30f;
                if (cb+1 > qr+8) sc[jn][3] = -1e30f;
            }
        }

        // online softmax (rows qr and qr+8 per thread-quad)
        float mx0 = -1e30f, mx1 = -1e30f;
        #pragma unroll
        for (int jn = 0; jn < 8; jn++){
            mx0 = fmaxf(mx0, fmaxf(sc[jn][0], sc[jn][1]));
            mx1 = fmaxf(mx1, fmaxf(sc[jn][2], sc[jn][3]));
        }
        mx0 = fmaxf(mx0, __shfl_xor_sync(0xffffffffu, mx0, 1));
        mx0 = fmaxf(mx0, __shfl_xor_sync(0xffffffffu, mx0, 2));
        mx1 = fmaxf(mx1, __shfl_xor_sync(0xffffffffu, mx1, 1));
        mx1 = fmaxf(mx1, __shfl_xor_sync(0xffffffffu, mx1, 2));

        float mn0 = fmaxf(mr0, mx0), mn1 = fmaxf(mr1, mx1);
        float al0 = __expf(mr0 - mn0), al1 = __expf(mr1 - mn1);
        mr0 = mn0; mr1 = mn1;

        float rs0 = 0.f, rs1 = 0.f;
        #pragma unroll
        for (int jn = 0; jn < 8; jn++){
            float p00 = __expf(sc[jn][0]-mn0), p01 = __expf(sc[jn][1]-mn0);
            float p10 = __expf(sc[jn][2]-mn1), p11 = __expf(sc[jn][3]-mn1);
            rs0 += p00 + p01; rs1 += p10 + p11;
            int pc = jn*8 + (lane & 3)*2;
            Ps[ pr   *PS_STRIDE + pc  ] = tf32r(p00);
            Ps[ pr   *PS_STRIDE + pc+1] = tf32r(p01);
            Ps[(pr+8)*PS_STRIDE + pc  ] = tf32r(p10);
            Ps[(pr+8)*PS_STRIDE + pc+1] = tf32r(p11);
        }
        rs0 += __shfl_xor_sync(0xffffffffu, rs0, 1);
        rs0 += __shfl_xor_sync(0xffffffffu, rs0, 2);
        rs1 += __shfl_xor_sync(0xffffffffu, rs1, 1);
        rs1 += __shfl_xor_sync(0xffffffffu, rs1, 2);
        l0 = l0*al0 + rs0;
        l1 = l1*al1 + rs1;

        #pragma unroll
        for (int jn = 0; jn < 8; jn++){
            o[jn][0]*=al0; o[jn][1]*=al0; o[jn][2]*=al1; o[jn][3]*=al1;
        }
        __syncwarp();

        // O += P @ V   (P rows are warp-private in smem)
        #pragma unroll
        for (int kf = 0; kf < 8; kf++){
            float a[4];
            int pc = kf*8 + (lane & 3);
            a[0] = Ps[ pr   *PS_STRIDE + pc    ];
            a[1] = Ps[(pr+8)*PS_STRIDE + pc    ];
            a[2] = Ps[ pr   *PS_STRIDE + pc + 4];
            a[3] = Ps[(pr+8)*PS_STRIDE + pc + 4];
            #pragma unroll
            for (int jn = 0; jn < 8; jn++){
                float b[2];
                int vr = kf*8 + (lane & 3);
                int vc = jn*8 + (lane >> 2);
                b[0] = Vs[ vr   *VS_STRIDE + vc];
                b[1] = Vs[(vr+4)*VS_STRIDE + vc];
                mma8(o[jn], a, b);
            }
        }
    }

    // finalize + write ctx in merged-head [B,S,D] layout
    float inv0 = 1.f / l0, inv1 = 1.f / l1;
    int bb = bh >> 4, hh = bh & (H_-1);
    float* C0 = g_ctx + ((size_t)bb*S_ + qr    )*D_ + hh*HD_;
    float* C1 = g_ctx + ((size_t)bb*S_ + qr + 8)*D_ + hh*HD_;
    #pragma unroll
    for (int jn = 0; jn < 8; jn++){
        int c = jn*8 + (lane & 3)*2;
        C0[c]   = o[jn][0]*inv0;
        C0[c+1] = o[jn][1]*inv0;
        C1[c]   = o[jn][2]*inv1;
        C1[c+1] = o[jn][3]*inv1;
    }
}

// ---------------------------------------------------------------------------
// Launch
// ---------------------------------------------------------------------------
extern "C" void kernel_launch(void* const* d_in, const int* in_sizes, int n_in,
                              void* d_out, int out_size)
{
    const float* q  = (const float*)d_in[0];
    const float* k  = (const float*)d_in[1];
    const float* v  = (const float*)d_in[2];
    // d_in[3] = mask: known causal, handled analytically
    const float* wq = (const float*)d_in[4];
    const float* bq = (const float*)d_in[5];
    const float* wk = (const float*)d_in[6];
    const float* bk = (const float*)d_in[7];
    const float* wv = (const float*)d_in[8];
    const float* bv = (const float*)d_in[9];
    const float* wo = (const float*)d_in[10];
    const float* bo = (const float*)d_in[11];
    float* out = (float*)d_out;

    cudaFuncSetAttribute(attn_kernel, cudaFuncAttributeMaxDynamicSharedMemorySize, ATTN_SMEM);

    dim3 gp(D_/128, TOK/128, 3);
    proj_kernel<<<gp, 256>>>(q, k, v, wq, wk, wv, bq, bk, bv);

    dim3 ga(S_/64, B_*H_);
    attn_kernel<<<ga, 128, ATTN_SMEM>>>();

    dim3 go(D_/128, TOK/128);
    outproj_kernel<<<go, 256>>>(wo, bo, out);
}

// round 2
// speedup vs baseline: 1.1527x; 1.1527x over previous
#include <cuda_runtime.h>
#include <cuda_bf16.h>
#include <cstdint>

// Problem constants
#define B_  2
#define S_  2048
#define D_  1024
#define H_  16
#define HD_ 64
#define TOK (B_*S_)   // 4096 tokens

// Scratch (allocation-free: __device__ globals)
__device__ float g_qp[B_*H_*S_*HD_];   // [B,H,S,HD]
__device__ float g_kp[B_*H_*S_*HD_];
__device__ float g_vp[B_*H_*S_*HD_];
__device__ float g_ctx[TOK*D_];        // [B,S,D] merged heads

// ---------------------------------------------------------------------------
// helpers
// ---------------------------------------------------------------------------
__device__ __forceinline__ float tf32r(float x){
    unsigned u; asm("cvt.rna.tf32.f32 %0, %1;" : "=r"(u) : "f"(x));
    return __uint_as_float(u);
}

__device__ __forceinline__ void mma8(float c[4], const float a[4], const float b[2]){
    asm volatile(
        "mma.sync.aligned.m16n8k8.row.col.f32.tf32.tf32.f32 "
        "{%0,%1,%2,%3},{%4,%5,%6,%7},{%8,%9},{%0,%1,%2,%3};\n"
        : "+f"(c[0]), "+f"(c[1]), "+f"(c[2]), "+f"(c[3])
        : "r"(__float_as_uint(a[0])), "r"(__float_as_uint(a[1])),
          "r"(__float_as_uint(a[2])), "r"(__float_as_uint(a[3])),
          "r"(__float_as_uint(b[0])), "r"(__float_as_uint(b[1])));
}

__device__ __forceinline__ void cpasync16(float* s, const float* g){
    unsigned sa = (unsigned)__cvta_generic_to_shared(s);
    asm volatile("cp.async.cg.shared.global [%0], [%1], 16;\n" :: "r"(sa), "l"(g));
}
#define CP_COMMIT() asm volatile("cp.async.commit_group;\n" ::: "memory")
#define CP_WAIT0()  asm volatile("cp.async.wait_group 0;\n" ::: "memory")

// ---------------------------------------------------------------------------
// GEMM core: C[M,N] = X[M,K] @ W[N,K]^T + bias, M=4096, N=K=1024.
// 128x128 block tile, BK=32, cp.async double buffered, 256 threads
// (8 warps, warp tile 64x32). Raw fp32 in smem; hi/lo tf32 split at
// fragment-load time (3-mma split accumulate for ~fp32 accuracy).
// SPLIT=true writes head-split layout [B,H,S,HD]; false writes [M,N].
// ---------------------------------------------------------------------------
#define SM_STRIDE 36
#define STAGE_F   (128*SM_STRIDE)
#define GEMM_SMEM (4*STAGE_F*4)     // 2 tiles x 2 stages x 4B = 73728 B

template<bool SPLIT>
__device__ __forceinline__ void gemm_core(const float* __restrict__ X,
                                          const float* __restrict__ W,
                                          const float* __restrict__ bias,
                                          float* __restrict__ C)
{
    extern __shared__ float dynsm[];
    float* As = dynsm;               // [2][128][36]
    float* Ws = dynsm + 2*STAGE_F;   // [2][128][36]

    const int tid  = threadIdx.x;
    const int lane = tid & 31;
    const int wrp  = tid >> 5;
    const int wm   = wrp & 1;        // 0..1  (M dir, 64 each)
    const int wn   = wrp >> 1;       // 0..3  (N dir, 32 each)
    const int m0   = blockIdx.y * 128;
    const int n0   = blockIdx.x * 128;

    float acc[4][4][4] = {};

    // stage loader: 128 rows x 32 floats per tile = 1024 float4; 4/thread/tile
    auto load_stage = [&](int k0, int buf){
        #pragma unroll
        for (int p = 0; p < 4; p++){
            int idx = tid + p*256;          // 0..1023
            int r   = idx >> 3;
            int cg  = (idx & 7) << 2;
            cpasync16(As + buf*STAGE_F + r*SM_STRIDE + cg,
                      X + (size_t)(m0+r)*D_ + k0 + cg);
            cpasync16(Ws + buf*STAGE_F + r*SM_STRIDE + cg,
                      W + (size_t)(n0+r)*D_ + k0 + cg);
        }
    };

    load_stage(0, 0);
    CP_COMMIT();

    int buf = 0;
    for (int k0 = 0; k0 < D_; k0 += 32){
        CP_WAIT0();
        __syncthreads();
        if (k0 + 32 < D_){
            load_stage(k0 + 32, buf ^ 1);
            CP_COMMIT();
        }

        const float* Ab = As + buf*STAGE_F;
        const float* Wb = Ws + buf*STAGE_F;

        #pragma unroll
        for (int kk = 0; kk < 4; kk++){
            const int kb = kk*8 + (lane & 3);
            float ah[4][4], al[4][4];
            #pragma unroll
            for (int mi = 0; mi < 4; mi++){
                int r = wm*64 + mi*16 + (lane >> 2);
                float x0 = Ab[ r   *SM_STRIDE + kb    ];
                float x1 = Ab[(r+8)*SM_STRIDE + kb    ];
                float x2 = Ab[ r   *SM_STRIDE + kb + 4];
                float x3 = Ab[(r+8)*SM_STRIDE + kb + 4];
                ah[mi][0] = tf32r(x0); al[mi][0] = tf32r(x0 - ah[mi][0]);
                ah[mi][1] = tf32r(x1); al[mi][1] = tf32r(x1 - ah[mi][1]);
                ah[mi][2] = tf32r(x2); al[mi][2] = tf32r(x2 - ah[mi][2]);
                ah[mi][3] = tf32r(x3); al[mi][3] = tf32r(x3 - ah[mi][3]);
            }
            #pragma unroll
            for (int ni = 0; ni < 4; ni++){
                int r = wn*32 + ni*8 + (lane >> 2);
                float y0 = Wb[r*SM_STRIDE + kb    ];
                float y1 = Wb[r*SM_STRIDE + kb + 4];
                float bh[2], bl[2];
                bh[0] = tf32r(y0); bl[0] = tf32r(y0 - bh[0]);
                bh[1] = tf32r(y1); bl[1] = tf32r(y1 - bh[1]);
                #pragma unroll
                for (int mi = 0; mi < 4; mi++){
                    mma8(acc[mi][ni], ah[mi], bh);
                    mma8(acc[mi][ni], ah[mi], bl);
                    mma8(acc[mi][ni], al[mi], bh);
                }
            }
        }
        buf ^= 1;
    }

    // epilogue (float2 stores; col pairs are adjacent)
    #pragma unroll
    for (int mi = 0; mi < 4; mi++){
        #pragma unroll
        for (int ni = 0; ni < 4; ni++){
            int mrow = m0 + wm*64 + mi*16 + (lane >> 2);
            int ncol = n0 + wn*32 + ni*8 + (lane & 3)*2;
            float b0 = bias[ncol], b1 = bias[ncol+1];
            #pragma unroll
            for (int half = 0; half < 2; half++){
                int row = mrow + half*8;
                float2 v = make_float2(acc[mi][ni][half*2+0] + b0,
                                       acc[mi][ni][half*2+1] + b1);
                if (SPLIT){
                    int b  = row >> 11;         // /S_
                    int s  = row & (S_-1);
                    int hh = ncol >> 6;         // /HD_
                    int hd = ncol & (HD_-1);
                    *reinterpret_cast<float2*>(
                        C + (((size_t)(b*H_+hh))*S_ + s)*HD_ + hd) = v;
                } else {
                    *reinterpret_cast<float2*>(C + (size_t)row*D_ + ncol) = v;
                }
            }
        }
    }
}

__global__ __launch_bounds__(256, 2) void proj_kernel(
    const float* __restrict__ xq, const float* __restrict__ xk, const float* __restrict__ xv,
    const float* __restrict__ wq, const float* __restrict__ wk, const float* __restrict__ wv,
    const float* __restrict__ bq, const float* __restrict__ bk, const float* __restrict__ bv)
{
    int z = blockIdx.z;
    const float* X    = (z==0) ? xq : (z==1) ? xk : xv;
    const float* W    = (z==0) ? wq : (z==1) ? wk : wv;
    const float* bias = (z==0) ? bq : (z==1) ? bk : bv;
    float*       C    = (z==0) ? g_qp : (z==1) ? g_kp : g_vp;
    gemm_core<true>(X, W, bias, C);
}

__global__ __launch_bounds__(256, 2) void outproj_kernel(
    const float* __restrict__ wo, const float* __restrict__ bo, float* __restrict__ out)
{
    gemm_core<false>(g_ctx, wo, bo, out);
}

// ---------------------------------------------------------------------------
// Flash attention, causal. One CTA = 64 q rows x one (b,h). 4 warps x 16 rows.
// tf32 single-pass QK^T and PV, fp32 online softmax. Causal tile skip (kt<=qt).
// ---------------------------------------------------------------------------
#define KS_STRIDE 68
#define VS_STRIDE 72
#define PS_STRIDE 68
#define ATTN_SMEM ((64*KS_STRIDE + 64*VS_STRIDE + 64*PS_STRIDE)*4)

__global__ __launch_bounds__(128) void attn_kernel()
{
    extern __shared__ float sm[];
    float* Ks = sm;
    float* Vs = sm + 64*KS_STRIDE;
    float* Ps = Vs + 64*VS_STRIDE;

    const int tid  = threadIdx.x;
    const int lane = tid & 31;
    const int wrp  = tid >> 5;
    const int qt   = blockIdx.x;
    const int bh   = blockIdx.y;

    const float* Qg = g_qp + (size_t)bh * S_ * HD_;
    const float* Kg = g_kp + (size_t)bh * S_ * HD_;
    const float* Vg = g_vp + (size_t)bh * S_ * HD_;

    const int qr = qt*64 + wrp*16 + (lane >> 2);   // global q row (pair base)
    const int pr = wrp*16 + (lane >> 2);           // local row within CTA

    // Q fragments resident in registers for the whole kernel (scale 1/8 folded in)
    float qa[8][4];
    #pragma unroll
    for (int kf = 0; kf < 8; kf++){
        int cc = kf*8 + (lane & 3);
        qa[kf][0] = tf32r(0.125f * Qg[(size_t)qr    *HD_ + cc    ]);
        qa[kf][1] = tf32r(0.125f * Qg[(size_t)(qr+8)*HD_ + cc    ]);
        qa[kf][2] = tf32r(0.125f * Qg[(size_t)qr    *HD_ + cc + 4]);
        qa[kf][3] = tf32r(0.125f * Qg[(size_t)(qr+8)*HD_ + cc + 4]);
    }

    float o[8][4] = {};
    float mr0 = -1e30f, mr1 = -1e30f, l0 = 0.f, l1 = 0.f;

    for (int kt = 0; kt <= qt; kt++){
        __syncthreads();
        #pragma unroll
        for (int p = 0; p < 8; p++){
            int flat = tid + p*128;                // 0..1023 float4 slots
            int r  = flat >> 4;
            int cg = (flat & 15) << 2;
            float4 k4 = *reinterpret_cast<const float4*>(Kg + (size_t)(kt*64+r)*HD_ + cg);
            float4 v4 = *reinterpret_cast<const float4*>(Vg + (size_t)(kt*64+r)*HD_ + cg);
            Ks[r*KS_STRIDE+cg+0]=tf32r(k4.x); Ks[r*KS_STRIDE+cg+1]=tf32r(k4.y);
            Ks[r*KS_STRIDE+cg+2]=tf32r(k4.z); Ks[r*KS_STRIDE+cg+3]=tf32r(k4.w);
            Vs[r*VS_STRIDE+cg+0]=tf32r(v4.x); Vs[r*VS_STRIDE+cg+1]=tf32r(v4.y);
            Vs[r*VS_STRIDE+cg+2]=tf32r(v4.z); Vs[r*VS_STRIDE+cg+3]=tf32r(v4.w);
        }
        __syncthreads();

        // scores: S = Q @ K^T  (64x64, K-dim = HD = 64)
        float sc[8][4] = {};
        #pragma unroll
        for (int kf = 0; kf < 8; kf++){
            #pragma unroll
            for (int jn = 0; jn < 8; jn++){
                float b[2];
                int krow = jn*8 + (lane >> 2);
                int kc   = kf*8 + (lane & 3);
                b[0] = Ks[krow*KS_STRIDE + kc];
                b[1] = Ks[krow*KS_STRIDE + kc + 4];
                mma8(sc[jn], qa[kf], b);
            }
        }

        // causal mask on diagonal tile only
        if (kt == qt){
            #pragma unroll
            for (int jn = 0; jn < 8; jn++){
                int cb = kt*64 + jn*8 + (lane & 3)*2;
                if (cb   > qr  ) sc[jn][0] = -1e30f;
                if (cb+1 > qr  ) sc[jn][1] = -1e30f;
                if (cb   > qr+8) sc[jn][2] = -1e30f;
                if (cb+1 > qr+8) sc[jn][3] = -1e30f;
            }
        }

        // online softmax (rows qr and qr+8 per thread-quad)
        float mx0 = -1e30f, mx1 = -1e30f;
        #pragma unroll
        for (int jn = 0; jn < 8; jn++){
            mx0 = fmaxf(mx0, fmaxf(sc[jn][0], sc[jn][1]));
            mx1 = fmaxf(mx1, fmaxf(sc[jn][2], sc[jn][3]));
        }
        mx0 = fmaxf(mx0, __shfl_xor_sync(0xffffffffu, mx0, 1));
        mx0 = fmaxf(mx0, __shfl_xor_sync(0xffffffffu, mx0, 2));
        mx1 = fmaxf(mx1, __shfl_xor_sync(0xffffffffu, mx1, 1));
        mx1 = fmaxf(mx1, __shfl_xor_sync(0xffffffffu, mx1, 2));

        float mn0 = fmaxf(mr0, mx0), mn1 = fmaxf(mr1, mx1);
        float al0 = __expf(mr0 - mn0), al1 = __expf(mr1 - mn1);
        mr0 = mn0; mr1 = mn1;

        float rs0 = 0.f, rs1 = 0.f;
        #pragma unroll
        for (int jn = 0; jn < 8; jn++){
            float p00 = __expf(sc[jn][0]-mn0), p01 = __expf(sc[jn][1]-mn0);
            float p10 = __expf(sc[jn][2]-mn1), p11 = __expf(sc[jn][3]-mn1);
            rs0 += p00 + p01; rs1 += p10 + p11;
            int pc = jn*8 + (lane & 3)*2;
            Ps[ pr   *PS_STRIDE + pc  ] = tf32r(p00);
            Ps[ pr   *PS_STRIDE + pc+1] = tf32r(p01);
            Ps[(pr+8)*PS_STRIDE + pc  ] = tf32r(p10);
            Ps[(pr+8)*PS_STRIDE + pc+1] = tf32r(p11);
        }
        rs0 += __shfl_xor_sync(0xffffffffu, rs0, 1);
        rs0 += __shfl_xor_sync(0xffffffffu, rs0, 2);
        rs1 += __shfl_xor_sync(0xffffffffu, rs1, 1);
        rs1 += __shfl_xor_sync(0xffffffffu, rs1, 2);
        l0 = l0*al0 + rs0;
        l1 = l1*al1 + rs1;

        #pragma unroll
        for (int jn = 0; jn < 8; jn++){
            o[jn][0]*=al0; o[jn][1]*=al0; o[jn][2]*=al1; o[jn][3]*=al1;
        }
        __syncwarp();

        // O += P @ V   (P rows are warp-private in smem)
        #pragma unroll
        for (int kf = 0; kf < 8; kf++){
            float a[4];
            int pc = kf*8 + (lane & 3);
            a[0] = Ps[ pr   *PS_STRIDE + pc    ];
            a[1] = Ps[(pr+8)*PS_STRIDE + pc    ];
            a[2] = Ps[ pr   *PS_STRIDE + pc + 4];
            a[3] = Ps[(pr+8)*PS_STRIDE + pc + 4];
            #pragma unroll
            for (int jn = 0; jn < 8; jn++){
                float b[2];
                int vr = kf*8 + (lane & 3);
                int vc = jn*8 + (lane >> 2);
                b[0] = Vs[ vr   *VS_STRIDE + vc];
                b[1] = Vs[(vr+4)*VS_STRIDE + vc];
                mma8(o[jn], a, b);
            }
        }
    }

    // finalize + write ctx in merged-head [B,S,D] layout
    float inv0 = 1.f / l0, inv1 = 1.f / l1;
    int bb = bh >> 4, hh = bh & (H_-1);
    float* C0 = g_ctx + ((size_t)bb*S_ + qr    )*D_ + hh*HD_;
    float* C1 = g_ctx + ((size_t)bb*S_ + qr + 8)*D_ + hh*HD_;
    #pragma unroll
    for (int jn = 0; jn < 8; jn++){
        int c = jn*8 + (lane & 3)*2;
        C0[c]   = o[jn][0]*inv0;
        C0[c+1] = o[jn][1]*inv0;
        C1[c]   = o[jn][2]*inv1;
        C1[c+1] = o[jn][3]*inv1;
    }
}

// ---------------------------------------------------------------------------
// Launch
// ---------------------------------------------------------------------------
extern "C" void kernel_launch(void* const* d_in, const int* in_sizes, int n_in,
                              void* d_out, int out_size)
{
    const float* q  = (const float*)d_in[0];
    const float* k  = (const float*)d_in[1];
    const float* v  = (const float*)d_in[2];
    // d_in[3] = mask: known causal, handled analytically
    const float* wq = (const float*)d_in[4];
    const float* bq = (const float*)d_in[5];
    const float* wk = (const float*)d_in[6];
    const float* bk = (const float*)d_in[7];
    const float* wv = (const float*)d_in[8];
    const float* bv = (const float*)d_in[9];
    const float* wo = (const float*)d_in[10];
    const float* bo = (const float*)d_in[11];
    float* out = (float*)d_out;

    cudaFuncSetAttribute(proj_kernel,    cudaFuncAttributeMaxDynamicSharedMemorySize, GEMM_SMEM);
    cudaFuncSetAttribute(outproj_kernel, cudaFuncAttributeMaxDynamicSharedMemorySize, GEMM_SMEM);
    cudaFuncSetAttribute(attn_kernel,    cudaFuncAttributeMaxDynamicSharedMemorySize, ATTN_SMEM);

    dim3 gp(D_/128, TOK/128, 3);
    proj_kernel<<<gp, 256, GEMM_SMEM>>>(q, k, v, wq, wk, wv, bq, bk, bv);

    dim3 ga(S_/64, B_*H_);
    attn_kernel<<<ga, 128, ATTN_SMEM>>>();

    dim3 go(D_/128, TOK/128);
    outproj_kernel<<<go, 256, GEMM_SMEM>>>(wo, bo, out);
}

// round 4
// speedup vs baseline: 1.8475x; 1.6028x over previous
#include <cuda_runtime.h>
#include <cuda_bf16.h>
#include <cstdint>

// Problem constants
#define B_  2
#define S_  2048
#define D_  1024
#define H_  16
#define HD_ 64
#define TOK (B_*S_)   // 4096 tokens

// ---------------------------------------------------------------------------
// Device scratch (allocation-free). bf16 hi/lo split operands for GEMMs.
// ---------------------------------------------------------------------------
__device__ __nv_bfloat16 g_xh[3][TOK*D_];   // split inputs (q,k,v)
__device__ __nv_bfloat16 g_xl[3][TOK*D_];
__device__ __nv_bfloat16 g_wh[4][D_*D_];    // split weights (wq,wk,wv,wo)
__device__ __nv_bfloat16 g_wl[4][D_*D_];
__device__ __nv_bfloat16 g_ch[TOK*D_];      // split ctx (written by attention)
__device__ __nv_bfloat16 g_cl[TOK*D_];
__device__ float g_qp[TOK*D_];              // projected, [B,H,S,HD]
__device__ float g_kp[TOK*D_];
__device__ float g_vp[TOK*D_];

// ---------------------------------------------------------------------------
// helpers
// ---------------------------------------------------------------------------
__device__ __forceinline__ float tf32r(float x){
    unsigned u; asm("cvt.rna.tf32.f32 %0, %1;" : "=r"(u) : "f"(x));
    return __uint_as_float(u);
}
__device__ __forceinline__ void cpa16(void* s, const void* g){
    unsigned sa = (unsigned)__cvta_generic_to_shared(s);
    asm volatile("cp.async.cg.shared.global [%0], [%1], 16;\n" :: "r"(sa), "l"(g));
}
#define CP_COMMIT() asm volatile("cp.async.commit_group;\n" ::: "memory")
#define CP_WAIT0()  asm volatile("cp.async.wait_group 0;\n" ::: "memory")

// bf16 m16n8k16 mma, fp32 accumulate
__device__ __forceinline__ void mma16(float c[4], const uint32_t a[4], const uint32_t b[2]){
    asm volatile(
        "mma.sync.aligned.m16n8k16.row.col.f32.bf16.bf16.f32 "
        "{%0,%1,%2,%3},{%4,%5,%6,%7},{%8,%9},{%0,%1,%2,%3};\n"
        : "+f"(c[0]), "+f"(c[1]), "+f"(c[2]), "+f"(c[3])
        : "r"(a[0]), "r"(a[1]), "r"(a[2]), "r"(a[3]), "r"(b[0]), "r"(b[1]));
}

// tf32 m16n8k8 mma (attention)
__device__ __forceinline__ void mma8(float c[4], const float a[4], const float b[2]){
    asm volatile(
        "mma.sync.aligned.m16n8k8.row.col.f32.tf32.tf32.f32 "
        "{%0,%1,%2,%3},{%4,%5,%6,%7},{%8,%9},{%0,%1,%2,%3};\n"
        : "+f"(c[0]), "+f"(c[1]), "+f"(c[2]), "+f"(c[3])
        : "r"(__float_as_uint(a[0])), "r"(__float_as_uint(a[1])),
          "r"(__float_as_uint(a[2])), "r"(__float_as_uint(a[3])),
          "r"(__float_as_uint(b[0])), "r"(__float_as_uint(b[1])));
}

// ---------------------------------------------------------------------------
// split kernel: bf16 hi/lo decomposition of 3 inputs + 4 weights
// ---------------------------------------------------------------------------
__global__ __launch_bounds__(256) void split_kernel(
    const float4* q, const float4* k, const float4* v,
    const float4* wq, const float4* wk, const float4* wv, const float4* wo)
{
    int which = blockIdx.z;
    int n8 = (which < 3) ? TOK*D_/8 : D_*D_/8;
    int i = blockIdx.x*256 + threadIdx.x;
    if (i >= n8) return;
    const float4* src;
    __nv_bfloat16 *hi, *lo;
    switch (which){
        case 0: src=q;  hi=g_xh[0]; lo=g_xl[0]; break;
        case 1: src=k;  hi=g_xh[1]; lo=g_xl[1]; break;
        case 2: src=v;  hi=g_xh[2]; lo=g_xl[2]; break;
        case 3: src=wq; hi=g_wh[0]; lo=g_wl[0]; break;
        case 4: src=wk; hi=g_wh[1]; lo=g_wl[1]; break;
        case 5: src=wv; hi=g_wh[2]; lo=g_wl[2]; break;
        default: src=wo; hi=g_wh[3]; lo=g_wl[3]; break;
    }
    float4 x0 = src[2*i], x1 = src[2*i+1];
    float f[8] = {x0.x,x0.y,x0.z,x0.w,x1.x,x1.y,x1.z,x1.w};
    alignas(16) __nv_bfloat16 hb[8], lb[8];
    #pragma unroll
    for (int j = 0; j < 8; j++){
        hb[j] = __float2bfloat16(f[j]);
        lb[j] = __float2bfloat16(f[j] - __bfloat162float(hb[j]));
    }
    reinterpret_cast<uint4*>(hi)[i] = *reinterpret_cast<uint4*>(hb);
    reinterpret_cast<uint4*>(lo)[i] = *reinterpret_cast<uint4*>(lb);
}

// ---------------------------------------------------------------------------
// bf16 split GEMM: C[M,N] = A @ Bw^T + bias  (M=4096, N=K=1024)
// 128x128 CTA tile, BK=32, cp.async double buffer, 256 threads, 8 warps
// (warp tile 64x32). 3-mma bf16 split (AhBh + AhBl + AlBh), fp32 accum.
// smem rows padded to 40 bf16 (80 B) -> conflict-free b32 fragment loads.
// ---------------------------------------------------------------------------
#define ROW_B   80                    // bytes per smem row (32 data bf16 + pad)
#define TILE_B  (128*ROW_B)           // 10240
#define STAGE_B (4*TILE_B)            // Ah, Al, Bh, Bl
#define GEMM_SMEM (2*STAGE_B)         // 81920

template<bool SPLIT>
__device__ __forceinline__ void gemm_core(
    const __nv_bfloat16* __restrict__ Ahp, const __nv_bfloat16* __restrict__ Alp,
    const __nv_bfloat16* __restrict__ Bhp, const __nv_bfloat16* __restrict__ Blp,
    const float* __restrict__ bias, float* __restrict__ C)
{
    extern __shared__ char smc[];

    const int tid  = threadIdx.x;
    const int lane = tid & 31;
    const int wrp  = tid >> 5;
    const int wm   = wrp & 1;        // 0..1  (M dir, 64 each)
    const int wn   = wrp >> 1;       // 0..3  (N dir, 32 each)
    const int m0   = blockIdx.y * 128;
    const int n0   = blockIdx.x * 128;

    float acc[4][4][4] = {};

    // stage one K-chunk (32 bf16 cols) of all 4 tiles into buffer `buf`
    auto stage = [&](int k0, int buf){
        char* base = smc + buf*STAGE_B;
        #pragma unroll
        for (int u = 0; u < 8; u++){
            int w    = tid + u*256;        // 0..2047
            int tile = w >> 9;
            int q    = w & 511;
            int r    = q >> 2;
            int ch   = q & 3;
            const __nv_bfloat16* src = (tile==0)?Ahp:(tile==1)?Alp:(tile==2)?Bhp:Blp;
            int rb = (tile < 2) ? m0 : n0;
            cpa16(base + tile*TILE_B + r*ROW_B + ch*16,
                  src + (size_t)(rb + r)*D_ + k0 + ch*8);
        }
    };

    stage(0, 0);
    CP_COMMIT();

    int buf = 0;
    for (int i = 0; i < 32; i++){
        CP_WAIT0();
        __syncthreads();
        if (i + 1 < 32){
            stage((i + 1)*32, buf ^ 1);
            CP_COMMIT();
        }

        const char* Ab = smc + buf*STAGE_B;
        const char* Lb = Ab + TILE_B;
        const char* Bb = Ab + 2*TILE_B;
        const char* Cb = Ab + 3*TILE_B;

        #pragma unroll
        for (int kk = 0; kk < 2; kk++){
            const int cb = kk*32 + (lane & 3)*4;   // byte col within row
            uint32_t ah[4][4], al[4][4];
            #pragma unroll
            for (int mi = 0; mi < 4; mi++){
                int r = wm*64 + mi*16 + (lane >> 2);
                int o = r*ROW_B + cb;
                ah[mi][0] = *(const uint32_t*)(Ab + o);
                ah[mi][1] = *(const uint32_t*)(Ab + o + 8*ROW_B);
                ah[mi][2] = *(const uint32_t*)(Ab + o + 16);
                ah[mi][3] = *(const uint32_t*)(Ab + o + 8*ROW_B + 16);
                al[mi][0] = *(const uint32_t*)(Lb + o);
                al[mi][1] = *(const uint32_t*)(Lb + o + 8*ROW_B);
                al[mi][2] = *(const uint32_t*)(Lb + o + 16);
                al[mi][3] = *(const uint32_t*)(Lb + o + 8*ROW_B + 16);
            }
            #pragma unroll
            for (int ni = 0; ni < 4; ni++){
                int r = wn*32 + ni*8 + (lane >> 2);
                int o = r*ROW_B + cb;
                uint32_t bh[2], bl[2];
                bh[0] = *(const uint32_t*)(Bb + o);
                bh[1] = *(const uint32_t*)(Bb + o + 16);
                bl[0] = *(const uint32_t*)(Cb + o);
                bl[1] = *(const uint32_t*)(Cb + o + 16);
                #pragma unroll
                for (int mi = 0; mi < 4; mi++){
                    mma16(acc[mi][ni], ah[mi], bh);
                    mma16(acc[mi][ni], ah[mi], bl);
                    mma16(acc[mi][ni], al[mi], bh);
                }
            }
        }
        buf ^= 1;
    }

    // epilogue (float2 stores; col pairs are adjacent)
    #pragma unroll
    for (int mi = 0; mi < 4; mi++){
        #pragma unroll
        for (int ni = 0; ni < 4; ni++){
            int mrow = m0 + wm*64 + mi*16 + (lane >> 2);
            int ncol = n0 + wn*32 + ni*8 + (lane & 3)*2;
            float b0 = bias[ncol], b1 = bias[ncol+1];
            #pragma unroll
            for (int half = 0; half < 2; half++){
                int row = mrow + half*8;
                float2 v = make_float2(acc[mi][ni][half*2+0] + b0,
                                       acc[mi][ni][half*2+1] + b1);
                if (SPLIT){
                    int b  = row >> 11;         // /S_
                    int s  = row & (S_-1);
                    int hh = ncol >> 6;         // /HD_
                    int hd = ncol & (HD_-1);
                    *reinterpret_cast<float2*>(
                        C + (((size_t)(b*H_+hh))*S_ + s)*HD_ + hd) = v;
                } else {
                    *reinterpret_cast<float2*>(C + (size_t)row*D_ + ncol) = v;
                }
            }
        }
    }
}

__global__ __launch_bounds__(256, 2) void proj_kernel(
    const float* __restrict__ bq, const float* __restrict__ bk, const float* __restrict__ bv)
{
    int z = blockIdx.z;
    const float* bias = (z==0) ? bq : (z==1) ? bk : bv;
    float* out = (z==0) ? g_qp : (z==1) ? g_kp : g_vp;
    gemm_core<true>(g_xh[z], g_xl[z], g_wh[z], g_wl[z], bias, out);
}

__global__ __launch_bounds__(256, 2) void outproj_kernel(
    const float* __restrict__ bo, float* __restrict__ out)
{
    gemm_core<false>(g_ch, g_cl, g_wh[3], g_wl[3], bo, out);
}

// ---------------------------------------------------------------------------
// Flash attention, causal. One CTA = 64 q rows x one (b,h). 4 warps x 16 rows.
// tf32 single-pass QK^T and PV, fp32 online softmax. Causal tile skip.
// Epilogue writes bf16 hi/lo ctx split directly.
// ---------------------------------------------------------------------------
#define KS_STRIDE 68
#define VS_STRIDE 72
#define PS_STRIDE 68
#define ATTN_SMEM ((64*KS_STRIDE + 64*VS_STRIDE + 64*PS_STRIDE)*4)

__global__ __launch_bounds__(128) void attn_kernel()
{
    extern __shared__ float sm[];
    float* Ks = sm;
    float* Vs = sm + 64*KS_STRIDE;
    float* Ps = Vs + 64*VS_STRIDE;

    const int tid  = threadIdx.x;
    const int lane = tid & 31;
    const int wrp  = tid >> 5;
    const int qt   = blockIdx.x;
    const int bh   = blockIdx.y;

    const float* Qg = g_qp + (size_t)bh * S_ * HD_;
    const float* Kg = g_kp + (size_t)bh * S_ * HD_;
    const float* Vg = g_vp + (size_t)bh * S_ * HD_;

    const int qr = qt*64 + wrp*16 + (lane >> 2);   // global q row (pair base)
    const int pr = wrp*16 + (lane >> 2);           // local row within CTA

    float qa[8][4];
    #pragma unroll
    for (int kf = 0; kf < 8; kf++){
        int cc = kf*8 + (lane & 3);
        qa[kf][0] = tf32r(0.125f * Qg[(size_t)qr    *HD_ + cc    ]);
        qa[kf][1] = tf32r(0.125f * Qg[(size_t)(qr+8)*HD_ + cc    ]);
        qa[kf][2] = tf32r(0.125f * Qg[(size_t)qr    *HD_ + cc + 4]);
        qa[kf][3] = tf32r(0.125f * Qg[(size_t)(qr+8)*HD_ + cc + 4]);
    }

    float o[8][4] = {};
    float mr0 = -1e30f, mr1 = -1e30f, l0 = 0.f, l1 = 0.f;

    for (int kt = 0; kt <= qt; kt++){
        __syncthreads();
        #pragma unroll
        for (int p = 0; p < 8; p++){
            int flat = tid + p*128;
            int r  = flat >> 4;
            int cg = (flat & 15) << 2;
            float4 k4 = *reinterpret_cast<const float4*>(Kg + (size_t)(kt*64+r)*HD_ + cg);
            float4 v4 = *reinterpret_cast<const float4*>(Vg + (size_t)(kt*64+r)*HD_ + cg);
            Ks[r*KS_STRIDE+cg+0]=tf32r(k4.x); Ks[r*KS_STRIDE+cg+1]=tf32r(k4.y);
            Ks[r*KS_STRIDE+cg+2]=tf32r(k4.z); Ks[r*KS_STRIDE+cg+3]=tf32r(k4.w);
            Vs[r*VS_STRIDE+cg+0]=tf32r(v4.x); Vs[r*VS_STRIDE+cg+1]=tf32r(v4.y);
            Vs[r*VS_STRIDE+cg+2]=tf32r(v4.z); Vs[r*VS_STRIDE+cg+3]=tf32r(v4.w);
        }
        __syncthreads();

        float sc[8][4] = {};
        #pragma unroll
        for (int kf = 0; kf < 8; kf++){
            #pragma unroll
            for (int jn = 0; jn < 8; jn++){
                float b[2];
                int krow = jn*8 + (lane >> 2);
                int kc   = kf*8 + (lane & 3);
                b[0] = Ks[krow*KS_STRIDE + kc];
                b[1] = Ks[krow*KS_STRIDE + kc + 4];
                mma8(sc[jn], qa[kf], b);
            }
        }

        if (kt == qt){
            #pragma unroll
            for (int jn = 0; jn < 8; jn++){
                int cb = kt*64 + jn*8 + (lane & 3)*2;
                if (cb   > qr  ) sc[jn][0] = -1e30f;
                if (cb+1 > qr  ) sc[jn][1] = -1e30f;
                if (cb   > qr+8) sc[jn][2] = -1e30f;
                if (cb+1 > qr+8) sc[jn][3] = -1e30f;
            }
        }

        float mx0 = -1e30f, mx1 = -1e30f;
        #pragma unroll
        for (int jn = 0; jn < 8; jn++){
            mx0 = fmaxf(mx0, fmaxf(sc[jn][0], sc[jn][1]));
            mx1 = fmaxf(mx1, fmaxf(sc[jn][2], sc[jn][3]));
        }
        mx0 = fmaxf(mx0, __shfl_xor_sync(0xffffffffu, mx0, 1));
        mx0 = fmaxf(mx0, __shfl_xor_sync(0xffffffffu, mx0, 2));
        mx1 = fmaxf(mx1, __shfl_xor_sync(0xffffffffu, mx1, 1));
        mx1 = fmaxf(mx1, __shfl_xor_sync(0xffffffffu, mx1, 2));

        float mn0 = fmaxf(mr0, mx0), mn1 = fmaxf(mr1, mx1);
        float al0 = __expf(mr0 - mn0), al1 = __expf(mr1 - mn1);
        mr0 = mn0; mr1 = mn1;

        float rs0 = 0.f, rs1 = 0.f;
        #pragma unroll
        for (int jn = 0; jn < 8; jn++){
            float p00 = __expf(sc[jn][0]-mn0), p01 = __expf(sc[jn][1]-mn0);
            float p10 = __expf(sc[jn][2]-mn1), p11 = __expf(sc[jn][3]-mn1);
            rs0 += p00 + p01; rs1 += p10 + p11;
            int pc = jn*8 + (lane & 3)*2;
            Ps[ pr   *PS_STRIDE + pc  ] = tf32r(p00);
            Ps[ pr   *PS_STRIDE + pc+1] = tf32r(p01);
            Ps[(pr+8)*PS_STRIDE + pc  ] = tf32r(p10);
            Ps[(pr+8)*PS_STRIDE + pc+1] = tf32r(p11);
        }
        rs0 += __shfl_xor_sync(0xffffffffu, rs0, 1);
        rs0 += __shfl_xor_sync(0xffffffffu, rs0, 2);
        rs1 += __shfl_xor_sync(0xffffffffu, rs1, 1);
        rs1 += __shfl_xor_sync(0xffffffffu, rs1, 2);
        l0 = l0*al0 + rs0;
        l1 = l1*al1 + rs1;

        #pragma unroll
        for (int jn = 0; jn < 8; jn++){
            o[jn][0]*=al0; o[jn][1]*=al0; o[jn][2]*=al1; o[jn][3]*=al1;
        }
        __syncwarp();

        #pragma unroll
        for (int kf = 0; kf < 8; kf++){
            float a[4];
            int pc = kf*8 + (lane & 3);
            a[0] = Ps[ pr   *PS_STRIDE + pc    ];
            a[1] = Ps[(pr+8)*PS_STRIDE + pc    ];
            a[2] = Ps[ pr   *PS_STRIDE + pc + 4];
            a[3] = Ps[(pr+8)*PS_STRIDE + pc + 4];
            #pragma unroll
            for (int jn = 0; jn < 8; jn++){
                float b[2];
                int vr = kf*8 + (lane & 3);
                int vc = jn*8 + (lane >> 2);
                b[0] = Vs[ vr   *VS_STRIDE + vc];
                b[1] = Vs[(vr+4)*VS_STRIDE + vc];
                mma8(o[jn], a, b);
            }
        }
    }

    // finalize + write bf16 hi/lo ctx split in merged-head [B,S,D] layout
    float inv0 = 1.f / l0, inv1 = 1.f / l1;
    int bb = bh >> 4, hh = bh & (H_-1);
    size_t base0 = ((size_t)bb*S_ + qr    )*D_ + hh*HD_;
    size_t base1 = ((size_t)bb*S_ + qr + 8)*D_ + hh*HD_;
    #pragma unroll
    for (int jn = 0; jn < 8; jn++){
        int c = jn*8 + (lane & 3)*2;
        float v00 = o[jn][0]*inv0, v01 = o[jn][1]*inv0;
        float v10 = o[jn][2]*inv1, v11 = o[jn][3]*inv1;
        __nv_bfloat162 h0, l0p, h1, l1p;
        h0.x  = __float2bfloat16(v00); h0.y  = __float2bfloat16(v01);
        l0p.x = __float2bfloat16(v00 - __bfloat162float(h0.x));
        l0p.y = __float2bfloat16(v01 - __bfloat162float(h0.y));
        h1.x  = __float2bfloat16(v10); h1.y  = __float2bfloat16(v11);
        l1p.x = __float2bfloat16(v10 - __bfloat162float(h1.x));
        l1p.y = __float2bfloat16(v11 - __bfloat162float(h1.y));
        *reinterpret_cast<__nv_bfloat162*>(g_ch + base0 + c) = h0;
        *reinterpret_cast<__nv_bfloat162*>(g_cl + base0 + c) = l0p;
        *reinterpret_cast<__nv_bfloat162*>(g_ch + base1 + c) = h1;
        *reinterpret_cast<__nv_bfloat162*>(g_cl + base1 + c) = l1p;
    }
}

// ---------------------------------------------------------------------------
// Launch
// ---------------------------------------------------------------------------
extern "C" void kernel_launch(void* const* d_in, const int* in_sizes, int n_in,
                              void* d_out, int out_size)
{
    const float4* q  = (const float4*)d_in[0];
    const float4* k  = (const float4*)d_in[1];
    const float4* v  = (const float4*)d_in[2];
    // d_in[3] = mask: causal, handled analytically
    const float4* wq = (const float4*)d_in[4];
    const float*  bq = (const float*)d_in[5];
    const float4* wk = (const float4*)d_in[6];
    const float*  bk = (const float*)d_in[7];
    const float4* wv = (const float4*)d_in[8];
    const float*  bv = (const float*)d_in[9];
    const float4* wo = (const float4*)d_in[10];
    const float*  bo = (const float*)d_in[11];
    float* out = (float*)d_out;

    cudaFuncSetAttribute(proj_kernel,    cudaFuncAttributeMaxDynamicSharedMemorySize, GEMM_SMEM);
    cudaFuncSetAttribute(outproj_kernel, cudaFuncAttributeMaxDynamicSharedMemorySize, GEMM_SMEM);
    cudaFuncSetAttribute(attn_kernel,    cudaFuncAttributeMaxDynamicSharedMemorySize, ATTN_SMEM);

    // split q,k,v + 4 weights into bf16 hi/lo (z = 0..6)
    {
        dim3 gs((TOK*D_/8 + 255)/256, 1, 7);
        split_kernel<<<gs, 256>>>(q, k, v, wq, wk, wv, wo);
    }

    // q/k/v projections
    {
        dim3 gp(D_/128, TOK/128, 3);
        proj_kernel<<<gp, 256, GEMM_SMEM>>>(bq, bk, bv);
    }

    // attention (writes bf16 ctx split)
    {
        dim3 ga(S_/64, B_*H_);
        attn_kernel<<<ga, 128, ATTN_SMEM>>>();
    }

    // output projection
    {
        dim3 go(D_/128, TOK/128);
        outproj_kernel<<<go, 256, GEMM_SMEM>>>(bo, out);
    }
}